// round 1
// baseline (speedup 1.0000x reference)
#include <cuda_runtime.h>
#include <cuda_bf16.h>
#include <cstdint>

// LightGraphConv: out[n,:] = ci[n] * sum_{e: dst[e]==n} src_feats[src[e],:] * cj[src[e]]
// N=100000 nodes, E=1600000 edges, D=32 features.
//
// Strategy: L2-resident atomic scatter.
//  - 8 lanes per edge, each handling one float4 (D=32 -> 8 float4 per row).
//  - red.global.add.v4.f32 for vectorized L2 reductions (4x fewer atomic ops).
//  - cj scaling fused into the scatter; ci scaling as a separate streaming pass.

__global__ void lgc_scatter_kernel(const float4* __restrict__ feats4,
                                   const float*  __restrict__ cj,
                                   const int*    __restrict__ src,
                                   const int*    __restrict__ dst,
                                   float4*       __restrict__ out4,
                                   int n_edges)
{
    int gid = blockIdx.x * blockDim.x + threadIdx.x;
    int e = gid >> 3;          // edge index
    int c = gid & 7;           // float4 chunk within the 32-float row
    if (e >= n_edges) return;

    int s = __ldg(src + e);
    int d = __ldg(dst + e);
    float w = __ldg(cj + s);

    float4 v = __ldg(feats4 + (long long)s * 8 + c);
    v.x *= w; v.y *= w; v.z *= w; v.w *= w;

    float4* p = out4 + (long long)d * 8 + c;
    asm volatile("red.global.add.v4.f32 [%0], {%1, %2, %3, %4};"
                 :: "l"(p), "f"(v.x), "f"(v.y), "f"(v.z), "f"(v.w)
                 : "memory");
}

__global__ void lgc_scale_kernel(float4* __restrict__ out4,
                                 const float* __restrict__ ci,
                                 int n_nodes)
{
    int gid = blockIdx.x * blockDim.x + threadIdx.x;   // one thread per float4
    int n = gid >> 3;
    if (n >= n_nodes) return;
    float s = __ldg(ci + n);
    float4 v = out4[gid];
    v.x *= s; v.y *= s; v.z *= s; v.w *= s;
    out4[gid] = v;
}

extern "C" void kernel_launch(void* const* d_in, const int* in_sizes, int n_in,
                              void* d_out, int out_size)
{
    const float* src_feats = (const float*)d_in[0];   // [N, 32]
    const float* cj        = (const float*)d_in[1];   // [N, 1]
    const float* ci        = (const float*)d_in[2];   // [N, 1]
    const int*   src_idx   = (const int*)  d_in[3];   // [E]
    const int*   dst_idx   = (const int*)  d_in[4];   // [E]
    float*       out       = (float*)d_out;           // [N, 32]

    const int N = in_sizes[1];
    const int E = in_sizes[3];

    // Zero the accumulator (d_out is poisoned before timing).
    cudaMemsetAsync(d_out, 0, (size_t)out_size * sizeof(float));

    // Edge scatter: 8 lanes per edge.
    {
        long long total = (long long)E * 8;
        int threads = 256;
        int blocks = (int)((total + threads - 1) / threads);
        lgc_scatter_kernel<<<blocks, threads>>>(
            (const float4*)src_feats, cj, src_idx, dst_idx, (float4*)out, E);
    }

    // Destination scaling.
    {
        long long total = (long long)N * 8;
        int threads = 256;
        int blocks = (int)((total + threads - 1) / threads);
        lgc_scale_kernel<<<blocks, threads>>>((float4*)out, ci, N);
    }
}